// round 9
// baseline (speedup 1.0000x reference)
#include <cuda_runtime.h>
#include <cstdint>

#define BB 4
#define CC 256
#define CI 128
#define TT 8192
#define NN 4096
#define BNT (BB*TT)

// Scratch (device globals; no allocation allowed)
__device__ float d_theta[BB*CI*TT];   // 16 MB (tf32-rounded values)
__device__ float d_phi[BB*CI*NN];     // 8 MB
__device__ float d_g[BB*CI*NN];       // 8 MB
__device__ float d_S[BB*CI*CI];       // 256 KB
__device__ float d_M[BB*CC*CI];       // 512 KB (tf32-rounded values)
__device__ float d_Th[BB*CI*CI];      // 256 KB  Theta = theta.theta^T per batch
__device__ float d_thsum[BB*CI];      // per (b,a) row sum of theta
__device__ float d_lin[CC];           // sum_b m.thsum
__device__ float d_q[CC];             // sum_b m^T Th m
__device__ float d_scale[CC];
__device__ float d_shift[CC];

// ---------------- tf32 helpers ----------------------------------------------
__device__ __forceinline__ float rnd_tf32(float v) {
    uint32_t t; asm("cvt.rn.tf32.f32 %0, %1;" : "=r"(t) : "f"(v));
    return __uint_as_float(t);
}
__device__ __forceinline__ void mma_tf32(float* d, const uint32_t* a, const uint32_t* b) {
    asm("mma.sync.aligned.m16n8k8.row.col.f32.tf32.tf32.f32 "
        "{%0,%1,%2,%3}, {%4,%5,%6,%7}, {%8,%9}, {%0,%1,%2,%3};"
        : "+f"(d[0]), "+f"(d[1]), "+f"(d[2]), "+f"(d[3])
        : "r"(a[0]), "r"(a[1]), "r"(a[2]), "r"(a[3]), "r"(b[0]), "r"(b[1]));
}

// ---------------- cp.async helpers ------------------------------------------
__device__ __forceinline__ uint32_t smem_u32(const void* p) {
    uint32_t a;
    asm("{ .reg .u64 t; cvta.to.shared.u64 t, %1; cvt.u32.u64 %0, t; }" : "=r"(a) : "l"(p));
    return a;
}
__device__ __forceinline__ void cp16(uint32_t dst, const void* src) {
    asm volatile("cp.async.cg.shared.global [%0], [%1], 16;" :: "r"(dst), "l"(src));
}
#define CP_COMMIT() asm volatile("cp.async.commit_group;" ::: "memory")
#define CP_WAIT1()  asm volatile("cp.async.wait_group 1;" ::: "memory")
#define CP_WAIT0()  asm volatile("cp.async.wait_group 0;" ::: "memory")

// SMEM geometry: per stage, A chunk 128 rows x 32 k (row-major, pad 4) and
// B chunk 32 k x 128 cols (pad 8). Two stages (double buffer).
#define RPA 36
#define RPB 136
#define ASZ (128*RPA)          // 4608 u32
#define BSZ (32*RPB)           // 4352 u32
#define STG_C (ASZ + BSZ)      // 8960 u32
#define SMEM_CONV (2*STG_C*4)  // 71680 B
#define STG_S (ASZ + ASZ)      // 9216 u32
#define SMEM_S (2*STG_S*4)     // 73728 B
// k_q smem: Th padded [128][129] + m[128] + ts[128] + red[16]
#define SMEM_Q ((128*129 + 128 + 128 + 16) * 4)

__device__ __forceinline__ void stage128x32(uint32_t dstb, const float* __restrict__ src,
                                            int lds, int koff, int tid) {
#pragma unroll
    for (int i = 0; i < 4; i++) {
        int fid = i * 256 + tid;
        int r = fid >> 3, q = fid & 7;
        cp16(dstb + (uint32_t)(r * RPA + q * 4) * 4,
             src + (size_t)r * lds + koff + q * 4);
    }
}
__device__ __forceinline__ void stage32x128(uint32_t dstb, const float* __restrict__ src,
                                            int lds, int koff, int t0, int tid) {
#pragma unroll
    for (int i = 0; i < 4; i++) {
        int fid = i * 256 + tid;
        int k = fid >> 5, t4 = (fid & 31) << 2;
        cp16(dstb + (uint32_t)(k * RPB + t4) * 4,
             src + (size_t)(koff + k) * lds + t0 + t4);
    }
}

// ---------------------------------------------------------------------------
// K0: zero accumulators (S, Th, thsum, lin, q).
// ---------------------------------------------------------------------------
__global__ void k_init() {
    int i = blockIdx.x * blockDim.x + threadIdx.x;   // 0..65535
    d_S[i]  = 0.0f;
    d_Th[i] = 0.0f;
    if (i < BB*CI) d_thsum[i] = 0.0f;
    if (i < CC) { d_lin[i] = 0.0f; d_q[i] = 0.0f; }
}

// ---------------------------------------------------------------------------
// K1: fused 1x1 convs via tf32 mma + cp.async. Block: 128 o x 128 t, K=256.
// theta path: tf32-RN rounding + fused theta row-sum atomics.
// ---------------------------------------------------------------------------
__global__ void __launch_bounds__(256, 2) k_conv_hmma(
    const float* __restrict__ x,
    const float* __restrict__ Wt, const float* __restrict__ bt,
    const float* __restrict__ Wp, const float* __restrict__ bp,
    const float* __restrict__ Wg, const float* __restrict__ bg)
{
    extern __shared__ uint32_t smem[];
    const uint32_t smb = smem_u32(smem);

    const int tid = threadIdx.x;
    const int warp = tid >> 5, lane = tid & 31;
    const int wo = warp >> 1, wt = warp & 1;
    const int b  = blockIdx.z;
    const int w  = blockIdx.y;
    const int t0 = blockIdx.x * 128;

    const float* W    = (w == 0) ? Wt : ((w == 1) ? Wp : Wg);
    const float* bias = (w == 0) ? bt : ((w == 1) ? bp : bg);
    const float* xb   = x + (size_t)b * CC * TT;

    float acc[2][8][4];
#pragma unroll
    for (int mi = 0; mi < 2; mi++)
#pragma unroll
        for (int nt = 0; nt < 8; nt++)
#pragma unroll
            for (int j = 0; j < 4; j++) acc[mi][nt][j] = 0.0f;

    const int lq = lane & 3, lr = lane >> 2;
    const int NC = 8;

    stage128x32(smb, W, CC, 0, tid);
    stage32x128(smb + ASZ * 4, xb, TT, 0, t0, tid);
    CP_COMMIT();

    for (int kc = 0; kc < NC; kc++) {
        if (kc + 1 < NC) {
            uint32_t ab = smb + (uint32_t)(((kc + 1) & 1) * STG_C) * 4;
            stage128x32(ab, W, CC, (kc + 1) * 32, tid);
            stage32x128(ab + ASZ * 4, xb, TT, (kc + 1) * 32, t0, tid);
            CP_COMMIT();
            CP_WAIT1();
        } else {
            CP_WAIT0();
        }
        __syncthreads();
        const uint32_t* As = smem + (kc & 1) * STG_C;
        const uint32_t* Bs = As + ASZ;
#pragma unroll
        for (int ks = 0; ks < 4; ks++) {
            int k0 = ks * 8;
            uint32_t a[2][4], bf[8][2];
#pragma unroll
            for (int mi = 0; mi < 2; mi++) {
                int ro = (wo * 2 + mi) * 16;
                a[mi][0] = As[(ro + lr) * RPA + k0 + lq];
                a[mi][1] = As[(ro + lr + 8) * RPA + k0 + lq];
                a[mi][2] = As[(ro + lr) * RPA + k0 + 4 + lq];
                a[mi][3] = As[(ro + lr + 8) * RPA + k0 + 4 + lq];
            }
            int tb = wt * 64 + lr;
#pragma unroll
            for (int nt = 0; nt < 8; nt++) {
                bf[nt][0] = Bs[(k0 + lq) * RPB + tb + nt * 8];
                bf[nt][1] = Bs[(k0 + 4 + lq) * RPB + tb + nt * 8];
            }
#pragma unroll
            for (int mi = 0; mi < 2; mi++)
#pragma unroll
                for (int nt = 0; nt < 8; nt++)
                    mma_tf32(acc[mi][nt], a[mi], bf[nt]);
        }
        __syncthreads();
    }

    if (w == 0) {
        float* dst = d_theta + (size_t)b * CI * TT;
#pragma unroll
        for (int mi = 0; mi < 2; mi++) {
            int o1 = wo * 32 + mi * 16 + lr;
            int o2 = o1 + 8;
            float bz1 = bias[o1], bz2 = bias[o2];
            float s1 = 0.f, s2 = 0.f;
#pragma unroll
            for (int nt = 0; nt < 8; nt++) {
                int t = t0 + wt * 64 + nt * 8 + 2 * lq;
                float v0 = rnd_tf32(acc[mi][nt][0] + bz1);
                float v1 = rnd_tf32(acc[mi][nt][1] + bz1);
                float v2 = rnd_tf32(acc[mi][nt][2] + bz2);
                float v3 = rnd_tf32(acc[mi][nt][3] + bz2);
                s1 += v0 + v1; s2 += v2 + v3;
                *(float2*)(dst + (size_t)o1 * TT + t) = make_float2(v0, v1);
                *(float2*)(dst + (size_t)o2 * TT + t) = make_float2(v2, v3);
            }
#pragma unroll
            for (int off = 1; off < 4; off <<= 1) {
                s1 += __shfl_xor_sync(0xffffffffu, s1, off);
                s2 += __shfl_xor_sync(0xffffffffu, s2, off);
            }
            if (lq == 0) {
                atomicAdd(&d_thsum[b * CI + o1], s1);
                atomicAdd(&d_thsum[b * CI + o2], s2);
            }
        }
    } else {
        float* dst = ((w == 1) ? d_phi : d_g) + (size_t)b * CI * NN;
#pragma unroll
        for (int mi = 0; mi < 2; mi++) {
            int o1 = wo * 32 + mi * 16 + lr;
            int o2 = o1 + 8;
            float bz1 = bias[o1], bz2 = bias[o2];
#pragma unroll
            for (int nt = 0; nt < 8; nt++) {
                int n = (t0 >> 1) + wt * 32 + nt * 4 + lq;
                dst[(size_t)o1 * NN + n] = fmaxf(acc[mi][nt][0], acc[mi][nt][1]) + bz1;
                dst[(size_t)o2 * NN + n] = fmaxf(acc[mi][nt][2], acc[mi][nt][3]) + bz2;
            }
        }
    }
}

// ---------------------------------------------------------------------------
// K2 (shared body): C[a][c] += sum_n A[a][n]*B[c][n] for 128x128 tiles,
// split-K over n, atomic reduce. Used for S (phi,g) and Th (theta,theta).
// ---------------------------------------------------------------------------
__device__ __forceinline__ void gram_body(const float* P, const float* G, int lds,
                                          int n0, float* Cp)
{
    extern __shared__ uint32_t smem[];
    const uint32_t smb = smem_u32(smem);
    const int tid = threadIdx.x;
    const int warp = tid >> 5, lane = tid & 31;
    const int wo = warp >> 1, wt = warp & 1;

    float acc[2][8][4];
#pragma unroll
    for (int mi = 0; mi < 2; mi++)
#pragma unroll
        for (int nt = 0; nt < 8; nt++)
#pragma unroll
            for (int j = 0; j < 4; j++) acc[mi][nt][j] = 0.0f;

    const int lq = lane & 3, lr = lane >> 2;
    const int NC = 8;

    stage128x32(smb, P, lds, n0, tid);
    stage128x32(smb + ASZ * 4, G, lds, n0, tid);
    CP_COMMIT();

    for (int kc = 0; kc < NC; kc++) {
        if (kc + 1 < NC) {
            uint32_t ab = smb + (uint32_t)(((kc + 1) & 1) * STG_S) * 4;
            stage128x32(ab, P, lds, n0 + (kc + 1) * 32, tid);
            stage128x32(ab + ASZ * 4, G, lds, n0 + (kc + 1) * 32, tid);
            CP_COMMIT();
            CP_WAIT1();
        } else {
            CP_WAIT0();
        }
        __syncthreads();
        const uint32_t* As  = smem + (kc & 1) * STG_S;
        const uint32_t* Bs2 = As + ASZ;
#pragma unroll
        for (int ks = 0; ks < 4; ks++) {
            int k0 = ks * 8;
            uint32_t a[2][4], bf[8][2];
#pragma unroll
            for (int mi = 0; mi < 2; mi++) {
                int ro = (wo * 2 + mi) * 16;
                a[mi][0] = As[(ro + lr) * RPA + k0 + lq];
                a[mi][1] = As[(ro + lr + 8) * RPA + k0 + lq];
                a[mi][2] = As[(ro + lr) * RPA + k0 + 4 + lq];
                a[mi][3] = As[(ro + lr + 8) * RPA + k0 + 4 + lq];
            }
#pragma unroll
            for (int nt = 0; nt < 8; nt++) {
                int n = wt * 64 + nt * 8 + lr;
                bf[nt][0] = Bs2[n * RPA + k0 + lq];
                bf[nt][1] = Bs2[n * RPA + k0 + 4 + lq];
            }
#pragma unroll
            for (int mi = 0; mi < 2; mi++)
#pragma unroll
                for (int nt = 0; nt < 8; nt++)
                    mma_tf32(acc[mi][nt], a[mi], bf[nt]);
        }
        __syncthreads();
    }

#pragma unroll
    for (int mi = 0; mi < 2; mi++) {
        int a1 = wo * 32 + mi * 16 + lr;
        int a2 = a1 + 8;
#pragma unroll
        for (int nt = 0; nt < 8; nt++) {
            int ci = wt * 64 + nt * 8 + 2 * lq;
            atomicAdd(&Cp[(size_t)a1 * CI + ci],     acc[mi][nt][0]);
            atomicAdd(&Cp[(size_t)a1 * CI + ci + 1], acc[mi][nt][1]);
            atomicAdd(&Cp[(size_t)a2 * CI + ci],     acc[mi][nt][2]);
            atomicAdd(&Cp[(size_t)a2 * CI + ci + 1], acc[mi][nt][3]);
        }
    }
}

__global__ void __launch_bounds__(256, 2) k_S_hmma()
{
    const int b = blockIdx.y;
    gram_body(d_phi + (size_t)b * CI * NN, d_g + (size_t)b * CI * NN, NN,
              blockIdx.x * 256, d_S + (size_t)b * CI * CI);
}

__global__ void __launch_bounds__(256, 2) k_T_hmma()
{
    const int b = blockIdx.y;
    const float* th = d_theta + (size_t)b * CI * TT;
    gram_body(th, th, TT, blockIdx.x * 256, d_Th + (size_t)b * CI * CI);
}

// ---------------------------------------------------------------------------
// K3: M[b,o,a] = round_tf32( (1/N) sum_k w_w[o,k] S[b,a,k] ).
// ---------------------------------------------------------------------------
__global__ __launch_bounds__(256) void k_M2(const float* __restrict__ ww)
{
    __shared__ float ws[32][129];
    __shared__ float ss[32][129];

    const int tid = threadIdx.x;
    const int b  = blockIdx.x >> 5;
    const int ob = (blockIdx.x >> 2) & 7;
    const int ab = blockIdx.x & 3;

#pragma unroll
    for (int i = 0; i < 4; i++) {
        int fid = i * 256 + tid;
        int r = fid >> 5, c4 = fid & 31;
        float4 v = *(const float4*)(ww + (size_t)(ob * 32 + r) * CI + 4 * c4);
        ws[r][4*c4+0] = v.x; ws[r][4*c4+1] = v.y; ws[r][4*c4+2] = v.z; ws[r][4*c4+3] = v.w;
        float4 u = *(const float4*)(d_S + (size_t)b * CI * CI + (size_t)(ab * 32 + r) * CI + 4 * c4);
        ss[r][4*c4+0] = u.x; ss[r][4*c4+1] = u.y; ss[r][4*c4+2] = u.z; ss[r][4*c4+3] = u.w;
    }
    __syncthreads();

    const int ty = tid >> 3;
    const int tx = tid & 7;
    float acc[4] = {0.f, 0.f, 0.f, 0.f};
#pragma unroll
    for (int k = 0; k < CI; k++) {
        float wv = ws[ty][k];
#pragma unroll
        for (int j = 0; j < 4; j++) acc[j] = fmaf(wv, ss[4*tx+j][k], acc[j]);
    }
    const float invN = 1.0f / NN;
    float* Mp = d_M + (size_t)b * CC * CI + (size_t)(ob * 32 + ty) * CI + ab * 32 + 4 * tx;
#pragma unroll
    for (int j = 0; j < 4; j++) Mp[j] = rnd_tf32(acc[j] * invN);
}

// ---------------------------------------------------------------------------
// K4: per (b, o): q = m^T Th_b m, lin = m . thsum_b. Accumulate over b.
// Grid (16 o-groups, 4 b), 128 threads. Th_b staged in padded smem.
// ---------------------------------------------------------------------------
__global__ void __launch_bounds__(128) k_q()
{
    extern __shared__ float smf[];
    float* ths = smf;                 // [128][129]
    float* smm = smf + 128 * 129;     // [128]
    float* sts = smm + 128;           // [128]
    float* red = sts + 128;           // [16]

    const int tid = threadIdx.x;
    const int og = blockIdx.x;
    const int b  = blockIdx.y;
    const int lane = tid & 31, warp = tid >> 5;

    const float* Thb = d_Th + (size_t)b * CI * CI;
#pragma unroll
    for (int i = 0; i < 32; i++) {
        int fid = i * 128 + tid;           // 0..4095 float4
        int r = fid >> 5, c4 = (fid & 31) * 4;
        float4 v = *(const float4*)(Thb + (size_t)r * CI + c4);
        ths[r * 129 + c4 + 0] = v.x; ths[r * 129 + c4 + 1] = v.y;
        ths[r * 129 + c4 + 2] = v.z; ths[r * 129 + c4 + 3] = v.w;
    }
    sts[tid] = d_thsum[b * CI + tid];
    __syncthreads();

    for (int oi = 0; oi < 16; oi++) {
        int o = og * 16 + oi;
        smm[tid] = d_M[(size_t)b * CC * CI + (size_t)o * CI + tid];
        __syncthreads();
        float accq = 0.0f;
        const float* row = ths + tid * 129;
#pragma unroll 8
        for (int c = 0; c < CI; c++) accq = fmaf(row[c], smm[c], accq);
        float q = accq * smm[tid];
        float s = smm[tid] * sts[tid];
#pragma unroll
        for (int off = 16; off > 0; off >>= 1) {
            q += __shfl_xor_sync(0xffffffffu, q, off);
            s += __shfl_xor_sync(0xffffffffu, s, off);
        }
        if (lane == 0) { red[warp] = q; red[warp + 8] = s; }
        __syncthreads();
        if (tid == 0) {
            atomicAdd(&d_q[o],   red[0] + red[1] + red[2] + red[3]);
            atomicAdd(&d_lin[o], red[8] + red[9] + red[10] + red[11]);
        }
        __syncthreads();
    }
}

// ---------------------------------------------------------------------------
// K5: finalize BN stats from analytic moments.
// ---------------------------------------------------------------------------
__global__ void k_stats(const float* __restrict__ wb,
                        const float* __restrict__ gamma,
                        const float* __restrict__ beta)
{
    int o = threadIdx.x;
    if (o < CC) {
        float w = wb[o];
        float lin = d_lin[o];
        float mean = (lin + (float)BNT * w) * (1.0f / BNT);
        float ewy2 = (d_q[o] + 2.0f * w * lin) * (1.0f / BNT) + w * w;
        float var  = ewy2 - mean * mean;
        float sc   = gamma[o] * rsqrtf(var + 1e-5f);
        d_scale[o] = sc;
        d_shift[o] = beta[o] - mean * sc + sc * w;   // folds w_b into shift
    }
}

// ---------------------------------------------------------------------------
// K6: out = scale[o]*(M.theta) + shift[o] + x   (fused GEMM + BN + residual)
// ---------------------------------------------------------------------------
__global__ void __launch_bounds__(256, 2) k_fout(const float* __restrict__ x,
                                                 float* __restrict__ out)
{
    extern __shared__ uint32_t smem[];
    const uint32_t smb = smem_u32(smem);

    const int tid = threadIdx.x;
    const int warp = tid >> 5, lane = tid & 31;
    const int wo = warp >> 1, wt = warp & 1;
    const int b  = blockIdx.z;
    const int o0 = blockIdx.y * 128;
    const int t0 = blockIdx.x * 128;

    const float* Mp = d_M + (size_t)b * CC * CI + (size_t)o0 * CI;
    const float* Th = d_theta + (size_t)b * CI * TT;

    float acc[2][8][4];
#pragma unroll
    for (int mi = 0; mi < 2; mi++)
#pragma unroll
        for (int nt = 0; nt < 8; nt++)
#pragma unroll
            for (int j = 0; j < 4; j++) acc[mi][nt][j] = 0.0f;

    const int lq = lane & 3, lr = lane >> 2;
    const int NC = 4;

    stage128x32(smb, Mp, CI, 0, tid);
    stage32x128(smb + ASZ * 4, Th, TT, 0, t0, tid);
    CP_COMMIT();

    for (int kc = 0; kc < NC; kc++) {
        if (kc + 1 < NC) {
            uint32_t ab = smb + (uint32_t)(((kc + 1) & 1) * STG_C) * 4;
            stage128x32(ab, Mp, CI, (kc + 1) * 32, tid);
            stage32x128(ab + ASZ * 4, Th, TT, (kc + 1) * 32, t0, tid);
            CP_COMMIT();
            CP_WAIT1();
        } else {
            CP_WAIT0();
        }
        __syncthreads();
        const uint32_t* As = smem + (kc & 1) * STG_C;
        const uint32_t* Bs = As + ASZ;
#pragma unroll
        for (int ks = 0; ks < 4; ks++) {
            int k0 = ks * 8;
            uint32_t a[2][4], bf[8][2];
#pragma unroll
            for (int mi = 0; mi < 2; mi++) {
                int ro = (wo * 2 + mi) * 16;
                a[mi][0] = As[(ro + lr) * RPA + k0 + lq];
                a[mi][1] = As[(ro + lr + 8) * RPA + k0 + lq];
                a[mi][2] = As[(ro + lr) * RPA + k0 + 4 + lq];
                a[mi][3] = As[(ro + lr + 8) * RPA + k0 + 4 + lq];
            }
            int tb = wt * 64 + lr;
#pragma unroll
            for (int nt = 0; nt < 8; nt++) {
                bf[nt][0] = Bs[(k0 + lq) * RPB + tb + nt * 8];
                bf[nt][1] = Bs[(k0 + 4 + lq) * RPB + tb + nt * 8];
            }
#pragma unroll
            for (int mi = 0; mi < 2; mi++)
#pragma unroll
                for (int nt = 0; nt < 8; nt++)
                    mma_tf32(acc[mi][nt], a[mi], bf[nt]);
        }
        __syncthreads();
    }

#pragma unroll
    for (int mi = 0; mi < 2; mi++) {
        int o1 = o0 + wo * 32 + mi * 16 + lr;
        int o2 = o1 + 8;
        float sc1 = d_scale[o1], sh1 = d_shift[o1];
        float sc2 = d_scale[o2], sh2 = d_shift[o2];
        const float* x1 = x + ((size_t)b * CC + o1) * TT;
        const float* x2 = x + ((size_t)b * CC + o2) * TT;
        float* d1 = out + ((size_t)b * CC + o1) * TT;
        float* d2 = out + ((size_t)b * CC + o2) * TT;
#pragma unroll
        for (int nt = 0; nt < 8; nt++) {
            int t = t0 + wt * 64 + nt * 8 + 2 * lq;
            float2 xv1 = *(const float2*)(x1 + t);
            float2 xv2 = *(const float2*)(x2 + t);
            *(float2*)(d1 + t) = make_float2(fmaf(sc1, acc[mi][nt][0], sh1) + xv1.x,
                                             fmaf(sc1, acc[mi][nt][1], sh1) + xv1.y);
            *(float2*)(d2 + t) = make_float2(fmaf(sc2, acc[mi][nt][2], sh2) + xv2.x,
                                             fmaf(sc2, acc[mi][nt][3], sh2) + xv2.y);
        }
    }
}

// ---------------------------------------------------------------------------
extern "C" void kernel_launch(void* const* d_in, const int* in_sizes, int n_in,
                              void* d_out, int out_size)
{
    const float* x     = (const float*)d_in[0];
    const float* tw    = (const float*)d_in[1];
    const float* tb    = (const float*)d_in[2];
    const float* pw    = (const float*)d_in[3];
    const float* pb    = (const float*)d_in[4];
    const float* gw    = (const float*)d_in[5];
    const float* gb    = (const float*)d_in[6];
    const float* ww    = (const float*)d_in[7];
    const float* wb    = (const float*)d_in[8];
    const float* gamma = (const float*)d_in[9];
    const float* beta  = (const float*)d_in[10];
    float* out = (float*)d_out;

    static int smem_set = 0;
    if (!smem_set) {
        cudaFuncSetAttribute(k_conv_hmma, cudaFuncAttributeMaxDynamicSharedMemorySize, SMEM_CONV);
        cudaFuncSetAttribute(k_S_hmma,    cudaFuncAttributeMaxDynamicSharedMemorySize, SMEM_S);
        cudaFuncSetAttribute(k_T_hmma,    cudaFuncAttributeMaxDynamicSharedMemorySize, SMEM_S);
        cudaFuncSetAttribute(k_q,         cudaFuncAttributeMaxDynamicSharedMemorySize, SMEM_Q);
        cudaFuncSetAttribute(k_fout,      cudaFuncAttributeMaxDynamicSharedMemorySize, SMEM_CONV);
        smem_set = 1;
    }

    k_init<<<256, 256>>>();
    k_conv_hmma<<<dim3(TT / 128, 3, BB), 256, SMEM_CONV>>>(x, tw, tb, pw, pb, gw, gb);
    k_S_hmma<<<dim3(16, BB), 256, SMEM_S>>>();
    k_T_hmma<<<dim3(32, BB), 256, SMEM_S>>>();
    k_M2<<<128, 256>>>(ww);
    k_q<<<dim3(16, BB), 128, SMEM_Q>>>();
    k_stats<<<1, 256>>>(wb, gamma, beta);
    k_fout<<<dim3(TT / 128, 2, BB), 256, SMEM_CONV>>>(x, out);
}

// round 10
// speedup vs baseline: 1.2261x; 1.2261x over previous
#include <cuda_runtime.h>
#include <cstdint>

#define BB 4
#define CC 256
#define CI 128
#define TT 8192
#define NN 4096
#define BNT (BB*TT)

// Scratch (device globals; no allocation allowed)
__device__ float d_theta[BB*CI*TT];   // 16 MB
__device__ float d_phi[BB*CI*NN];     // 8 MB
__device__ float d_g[BB*CI*NN];       // 8 MB
__device__ float d_S[BB*CI*CI];       // 256 KB
__device__ float d_M[BB*CC*CI];       // 512 KB
__device__ float d_wy[BB*CC*TT];      // 32 MB
__device__ float d_sum[CC];
__device__ float d_sumsq[CC];
__device__ float d_scale[CC];
__device__ float d_shift[CC];

// ---------------- tf32 mma.sync helper (raw fp32 bits; BN cancels the
// systematic truncation bias as a per-channel affine distortion) ------------
__device__ __forceinline__ void mma_tf32(float* d, const uint32_t* a, const uint32_t* b) {
    asm("mma.sync.aligned.m16n8k8.row.col.f32.tf32.tf32.f32 "
        "{%0,%1,%2,%3}, {%4,%5,%6,%7}, {%8,%9}, {%0,%1,%2,%3};"
        : "+f"(d[0]), "+f"(d[1]), "+f"(d[2]), "+f"(d[3])
        : "r"(a[0]), "r"(a[1]), "r"(a[2]), "r"(a[3]), "r"(b[0]), "r"(b[1]));
}

// ---------------- cp.async helpers ------------------------------------------
__device__ __forceinline__ uint32_t smem_u32(const void* p) {
    uint32_t a;
    asm("{ .reg .u64 t; cvta.to.shared.u64 t, %1; cvt.u32.u64 %0, t; }" : "=r"(a) : "l"(p));
    return a;
}
__device__ __forceinline__ void cp16(uint32_t dst, const void* src) {
    asm volatile("cp.async.cg.shared.global [%0], [%1], 16;" :: "r"(dst), "l"(src));
}
#define CP_COMMIT() asm volatile("cp.async.commit_group;" ::: "memory")
#define CP_WAIT2()  asm volatile("cp.async.wait_group 2;" ::: "memory")
#define CP_WAIT1()  asm volatile("cp.async.wait_group 1;" ::: "memory")
#define CP_WAIT0()  asm volatile("cp.async.wait_group 0;" ::: "memory")

// SMEM geometry: per stage, A chunk 128 rows x 32 k (row-major, pad 4) and
// B chunk 32 k x 128 cols (pad 8). THREE stages (triple buffer).
//   A frag loads: bank = (4*lr + lq + 8ks) % 32  -> conflict-free
//   B frag loads: bank = (8*lq + lr) % 32        -> conflict-free
//   gram B (row-major like A): bank = (4*lr + lq) -> conflict-free
#define RPA 36
#define RPB 136
#define ASZ (128*RPA)           // 4608 u32
#define BSZ (32*RPB)            // 4352 u32
#define STG_C (ASZ + BSZ)       // 8960 u32
#define SMEM_C3 (3*STG_C*4)     // 107520 B
#define STG_S (ASZ + ASZ)       // 9216 u32
#define SMEM_S3 (3*STG_S*4)     // 110592 B

// Stage 128 rows x 32 floats (A-style / gram-B-style), cp.async.
__device__ __forceinline__ void stage128x32(uint32_t dstb, const float* __restrict__ src,
                                            int lds, int koff, int tid) {
#pragma unroll
    for (int i = 0; i < 4; i++) {
        int fid = i * 256 + tid;
        int r = fid >> 3, q = fid & 7;
        cp16(dstb + (uint32_t)(r * RPA + q * 4) * 4,
             src + (size_t)r * lds + koff + q * 4);
    }
}
// Stage 32 k-rows x 128 floats (B-style), cp.async.
__device__ __forceinline__ void stage32x128(uint32_t dstb, const float* __restrict__ src,
                                            int lds, int koff, int t0, int tid) {
#pragma unroll
    for (int i = 0; i < 4; i++) {
        int fid = i * 256 + tid;
        int k = fid >> 5, t4 = (fid & 31) << 2;
        cp16(dstb + (uint32_t)(k * RPB + t4) * 4,
             src + (size_t)(koff + k) * lds + t0 + t4);
    }
}

// ---------------------------------------------------------------------------
// K0: zero accumulators (S, sum, sumsq).
// ---------------------------------------------------------------------------
__global__ void k_init() {
    int i = blockIdx.x * blockDim.x + threadIdx.x;   // 0..65535
    if (i < BB*CI*CI) d_S[i] = 0.0f;
    if (i < CC) { d_sum[i] = 0.0f; d_sumsq[i] = 0.0f; }
}

// ---------------------------------------------------------------------------
// K1: fused 1x1 convs via tf32 mma + 3-stage cp.async pipeline.
// Block: 128 o x 128 t, K=256 in 8 chunks of 32.
// ---------------------------------------------------------------------------
__global__ void __launch_bounds__(256, 2) k_conv_hmma(
    const float* __restrict__ x,
    const float* __restrict__ Wt, const float* __restrict__ bt,
    const float* __restrict__ Wp, const float* __restrict__ bp,
    const float* __restrict__ Wg, const float* __restrict__ bg)
{
    extern __shared__ uint32_t smem[];
    const uint32_t smb = smem_u32(smem);

    const int tid = threadIdx.x;
    const int warp = tid >> 5, lane = tid & 31;
    const int wo = warp >> 1, wt = warp & 1;
    const int b  = blockIdx.z;
    const int w  = blockIdx.y;
    const int t0 = blockIdx.x * 128;

    const float* W    = (w == 0) ? Wt : ((w == 1) ? Wp : Wg);
    const float* bias = (w == 0) ? bt : ((w == 1) ? bp : bg);
    const float* xb   = x + (size_t)b * CC * TT;

    float acc[2][8][4];
#pragma unroll
    for (int mi = 0; mi < 2; mi++)
#pragma unroll
        for (int nt = 0; nt < 8; nt++)
#pragma unroll
            for (int j = 0; j < 4; j++) acc[mi][nt][j] = 0.0f;

    const int lq = lane & 3, lr = lane >> 2;
    const int NC = 8;

    // prologue: stage chunks 0 and 1
    stage128x32(smb, W, CC, 0, tid);
    stage32x128(smb + ASZ * 4, xb, TT, 0, t0, tid);
    CP_COMMIT();
    stage128x32(smb + (uint32_t)STG_C * 4, W, CC, 32, tid);
    stage32x128(smb + (uint32_t)(STG_C + ASZ) * 4, xb, TT, 32, t0, tid);
    CP_COMMIT();

    for (int kc = 0; kc < NC; kc++) {
        if (kc + 2 < NC) {
            uint32_t ab = smb + (uint32_t)(((kc + 2) % 3) * STG_C) * 4;
            stage128x32(ab, W, CC, (kc + 2) * 32, tid);
            stage32x128(ab + ASZ * 4, xb, TT, (kc + 2) * 32, t0, tid);
            CP_COMMIT();
            CP_WAIT2();
        } else if (kc + 1 < NC) {
            CP_WAIT1();
        } else {
            CP_WAIT0();
        }
        __syncthreads();
        const uint32_t* As = smem + (kc % 3) * STG_C;
        const uint32_t* Bs = As + ASZ;
#pragma unroll
        for (int ks = 0; ks < 4; ks++) {
            int k0 = ks * 8;
            uint32_t a[2][4], bf[8][2];
#pragma unroll
            for (int mi = 0; mi < 2; mi++) {
                int ro = (wo * 2 + mi) * 16;
                a[mi][0] = As[(ro + lr) * RPA + k0 + lq];
                a[mi][1] = As[(ro + lr + 8) * RPA + k0 + lq];
                a[mi][2] = As[(ro + lr) * RPA + k0 + 4 + lq];
                a[mi][3] = As[(ro + lr + 8) * RPA + k0 + 4 + lq];
            }
            int tb = wt * 64 + lr;
#pragma unroll
            for (int nt = 0; nt < 8; nt++) {
                bf[nt][0] = Bs[(k0 + lq) * RPB + tb + nt * 8];
                bf[nt][1] = Bs[(k0 + 4 + lq) * RPB + tb + nt * 8];
            }
#pragma unroll
            for (int mi = 0; mi < 2; mi++)
#pragma unroll
                for (int nt = 0; nt < 8; nt++)
                    mma_tf32(acc[mi][nt], a[mi], bf[nt]);
        }
        __syncthreads();
    }

    // Epilogue. D frag: d0=D[lr][2lq], d1=D[lr][2lq+1], d2=D[lr+8][2lq], d3=D[lr+8][2lq+1]
    if (w == 0) {
        float* dst = d_theta + (size_t)b * CI * TT;
#pragma unroll
        for (int mi = 0; mi < 2; mi++) {
            int o1 = wo * 32 + mi * 16 + lr;
            int o2 = o1 + 8;
            float bz1 = bias[o1], bz2 = bias[o2];
#pragma unroll
            for (int nt = 0; nt < 8; nt++) {
                int t = t0 + wt * 64 + nt * 8 + 2 * lq;
                *(float2*)(dst + (size_t)o1 * TT + t) =
                    make_float2(acc[mi][nt][0] + bz1, acc[mi][nt][1] + bz1);
                *(float2*)(dst + (size_t)o2 * TT + t) =
                    make_float2(acc[mi][nt][2] + bz2, acc[mi][nt][3] + bz2);
            }
        }
    } else {
        float* dst = ((w == 1) ? d_phi : d_g) + (size_t)b * CI * NN;
#pragma unroll
        for (int mi = 0; mi < 2; mi++) {
            int o1 = wo * 32 + mi * 16 + lr;
            int o2 = o1 + 8;
            float bz1 = bias[o1], bz2 = bias[o2];
#pragma unroll
            for (int nt = 0; nt < 8; nt++) {
                int n = (t0 >> 1) + wt * 32 + nt * 4 + lq;
                dst[(size_t)o1 * NN + n] = fmaxf(acc[mi][nt][0], acc[mi][nt][1]) + bz1;
                dst[(size_t)o2 * NN + n] = fmaxf(acc[mi][nt][2], acc[mi][nt][3]) + bz2;
            }
        }
    }
}

// ---------------------------------------------------------------------------
// Gram-style GEMM body: C[a][c] (+)= sum_n A[a][n]*B[c][n], 128x128 tile,
// NC chunks of 32, 3-stage pipeline. ATOMIC: atomicAdd; else direct store
// scaled by cscale. Used by k_S (phi,g split-K) and k_M3 (ww,S full-K).
// ---------------------------------------------------------------------------
template<int NC, bool ATOMIC>
__device__ __forceinline__ void gram3(const float* __restrict__ P,
                                      const float* __restrict__ G,
                                      int ldp, int ldg, int n0,
                                      float* __restrict__ Cp, float cscale)
{
    extern __shared__ uint32_t smem[];
    const uint32_t smb = smem_u32(smem);
    const int tid = threadIdx.x;
    const int warp = tid >> 5, lane = tid & 31;
    const int wo = warp >> 1, wt = warp & 1;

    float acc[2][8][4];
#pragma unroll
    for (int mi = 0; mi < 2; mi++)
#pragma unroll
        for (int nt = 0; nt < 8; nt++)
#pragma unroll
            for (int j = 0; j < 4; j++) acc[mi][nt][j] = 0.0f;

    const int lq = lane & 3, lr = lane >> 2;

    stage128x32(smb, P, ldp, n0, tid);
    stage128x32(smb + ASZ * 4, G, ldg, n0, tid);
    CP_COMMIT();
    stage128x32(smb + (uint32_t)STG_S * 4, P, ldp, n0 + 32, tid);
    stage128x32(smb + (uint32_t)(STG_S + ASZ) * 4, G, ldg, n0 + 32, tid);
    CP_COMMIT();

    for (int kc = 0; kc < NC; kc++) {
        if (kc + 2 < NC) {
            uint32_t ab = smb + (uint32_t)(((kc + 2) % 3) * STG_S) * 4;
            stage128x32(ab, P, ldp, n0 + (kc + 2) * 32, tid);
            stage128x32(ab + ASZ * 4, G, ldg, n0 + (kc + 2) * 32, tid);
            CP_COMMIT();
            CP_WAIT2();
        } else if (kc + 1 < NC) {
            CP_WAIT1();
        } else {
            CP_WAIT0();
        }
        __syncthreads();
        const uint32_t* As  = smem + (kc % 3) * STG_S;
        const uint32_t* Bs2 = As + ASZ;
#pragma unroll
        for (int ks = 0; ks < 4; ks++) {
            int k0 = ks * 8;
            uint32_t a[2][4], bf[8][2];
#pragma unroll
            for (int mi = 0; mi < 2; mi++) {
                int ro = (wo * 2 + mi) * 16;
                a[mi][0] = As[(ro + lr) * RPA + k0 + lq];
                a[mi][1] = As[(ro + lr + 8) * RPA + k0 + lq];
                a[mi][2] = As[(ro + lr) * RPA + k0 + 4 + lq];
                a[mi][3] = As[(ro + lr + 8) * RPA + k0 + 4 + lq];
            }
#pragma unroll
            for (int nt = 0; nt < 8; nt++) {
                int n = wt * 64 + nt * 8 + lr;
                bf[nt][0] = Bs2[n * RPA + k0 + lq];
                bf[nt][1] = Bs2[n * RPA + k0 + 4 + lq];
            }
#pragma unroll
            for (int mi = 0; mi < 2; mi++)
#pragma unroll
                for (int nt = 0; nt < 8; nt++)
                    mma_tf32(acc[mi][nt], a[mi], bf[nt]);
        }
        __syncthreads();
    }

#pragma unroll
    for (int mi = 0; mi < 2; mi++) {
        int a1 = wo * 32 + mi * 16 + lr;
        int a2 = a1 + 8;
#pragma unroll
        for (int nt = 0; nt < 8; nt++) {
            int ci = wt * 64 + nt * 8 + 2 * lq;
            if (ATOMIC) {
                atomicAdd(&Cp[(size_t)a1 * CI + ci],     acc[mi][nt][0]);
                atomicAdd(&Cp[(size_t)a1 * CI + ci + 1], acc[mi][nt][1]);
                atomicAdd(&Cp[(size_t)a2 * CI + ci],     acc[mi][nt][2]);
                atomicAdd(&Cp[(size_t)a2 * CI + ci + 1], acc[mi][nt][3]);
            } else {
                *(float2*)(&Cp[(size_t)a1 * CI + ci]) =
                    make_float2(acc[mi][nt][0] * cscale, acc[mi][nt][1] * cscale);
                *(float2*)(&Cp[(size_t)a2 * CI + ci]) =
                    make_float2(acc[mi][nt][2] * cscale, acc[mi][nt][3] * cscale);
            }
        }
    }
}

// K2: S = phi.g^T (split-K over n, atomics)
__global__ void __launch_bounds__(256, 2) k_S_hmma()
{
    const int b = blockIdx.y;
    gram3<8, true>(d_phi + (size_t)b * CI * NN, d_g + (size_t)b * CI * NN,
                   NN, NN, blockIdx.x * 256, d_S + (size_t)b * CI * CI, 1.0f);
}

// K3: M = (1/N) ww.S^T  (full-K per block, direct store)
__global__ void __launch_bounds__(256, 2) k_M3(const float* __restrict__ ww)
{
    const int b  = blockIdx.y;
    const int o0 = blockIdx.x * 128;
    gram3<4, false>(ww + (size_t)o0 * CI, d_S + (size_t)b * CI * CI,
                    CI, CI, 0,
                    d_M + (size_t)b * CC * CI + (size_t)o0 * CI, 1.0f / NN);
}

// ---------------------------------------------------------------------------
// K4: wy = M @ theta + w_b via tf32 mma + 3-stage pipeline; fused BN sums.
// Block: 128 o x 128 t, K=128 in 4 chunks of 32.
// ---------------------------------------------------------------------------
__global__ void __launch_bounds__(256, 2) k_wy_hmma(const float* __restrict__ wb)
{
    extern __shared__ uint32_t smem[];
    const uint32_t smb = smem_u32(smem);

    const int tid = threadIdx.x;
    const int warp = tid >> 5, lane = tid & 31;
    const int wo = warp >> 1, wt = warp & 1;
    const int b  = blockIdx.z;
    const int o0 = blockIdx.y * 128;
    const int t0 = blockIdx.x * 128;

    const float* Mp = d_M + (size_t)b * CC * CI + (size_t)o0 * CI;
    const float* Th = d_theta + (size_t)b * CI * TT;

    float acc[2][8][4];
#pragma unroll
    for (int mi = 0; mi < 2; mi++)
#pragma unroll
        for (int nt = 0; nt < 8; nt++)
#pragma unroll
            for (int j = 0; j < 4; j++) acc[mi][nt][j] = 0.0f;

    const int lq = lane & 3, lr = lane >> 2;
    const int NC = 4;

    stage128x32(smb, Mp, CI, 0, tid);
    stage32x128(smb + ASZ * 4, Th, TT, 0, t0, tid);
    CP_COMMIT();
    stage128x32(smb + (uint32_t)STG_C * 4, Mp, CI, 32, tid);
    stage32x128(smb + (uint32_t)(STG_C + ASZ) * 4, Th, TT, 32, t0, tid);
    CP_COMMIT();

    for (int kc = 0; kc < NC; kc++) {
        if (kc + 2 < NC) {
            uint32_t ab = smb + (uint32_t)(((kc + 2) % 3) * STG_C) * 4;
            stage128x32(ab, Mp, CI, (kc + 2) * 32, tid);
            stage32x128(ab + ASZ * 4, Th, TT, (kc + 2) * 32, t0, tid);
            CP_COMMIT();
            CP_WAIT2();
        } else if (kc + 1 < NC) {
            CP_WAIT1();
        } else {
            CP_WAIT0();
        }
        __syncthreads();
        const uint32_t* As = smem + (kc % 3) * STG_C;
        const uint32_t* Bs = As + ASZ;
#pragma unroll
        for (int ks = 0; ks < 4; ks++) {
            int k0 = ks * 8;
            uint32_t a[2][4], bf[8][2];
#pragma unroll
            for (int mi = 0; mi < 2; mi++) {
                int ro = (wo * 2 + mi) * 16;
                a[mi][0] = As[(ro + lr) * RPA + k0 + lq];
                a[mi][1] = As[(ro + lr + 8) * RPA + k0 + lq];
                a[mi][2] = As[(ro + lr) * RPA + k0 + 4 + lq];
                a[mi][3] = As[(ro + lr + 8) * RPA + k0 + 4 + lq];
            }
            int tb = wt * 64 + lr;
#pragma unroll
            for (int nt = 0; nt < 8; nt++) {
                bf[nt][0] = Bs[(k0 + lq) * RPB + tb + nt * 8];
                bf[nt][1] = Bs[(k0 + 4 + lq) * RPB + tb + nt * 8];
            }
#pragma unroll
            for (int mi = 0; mi < 2; mi++)
#pragma unroll
                for (int nt = 0; nt < 8; nt++)
                    mma_tf32(acc[mi][nt], a[mi], bf[nt]);
        }
        __syncthreads();
    }

    float* wyp = d_wy + (size_t)b * CC * TT;
#pragma unroll
    for (int mi = 0; mi < 2; mi++) {
        int o1 = o0 + wo * 32 + mi * 16 + lr;
        int o2 = o1 + 8;
        float bz1 = wb[o1], bz2 = wb[o2];
        float s1 = 0.f, q1 = 0.f, s2 = 0.f, q2 = 0.f;
#pragma unroll
        for (int nt = 0; nt < 8; nt++) {
            int t = t0 + wt * 64 + nt * 8 + 2 * lq;
            float v0 = acc[mi][nt][0] + bz1, v1 = acc[mi][nt][1] + bz1;
            float v2 = acc[mi][nt][2] + bz2, v3 = acc[mi][nt][3] + bz2;
            s1 += v0 + v1; q1 = fmaf(v0, v0, q1); q1 = fmaf(v1, v1, q1);
            s2 += v2 + v3; q2 = fmaf(v2, v2, q2); q2 = fmaf(v3, v3, q2);
            *(float2*)(wyp + (size_t)o1 * TT + t) = make_float2(v0, v1);
            *(float2*)(wyp + (size_t)o2 * TT + t) = make_float2(v2, v3);
        }
#pragma unroll
        for (int off = 1; off < 4; off <<= 1) {
            s1 += __shfl_xor_sync(0xffffffffu, s1, off);
            q1 += __shfl_xor_sync(0xffffffffu, q1, off);
            s2 += __shfl_xor_sync(0xffffffffu, s2, off);
            q2 += __shfl_xor_sync(0xffffffffu, q2, off);
        }
        if (lq == 0) {
            atomicAdd(&d_sum[o1], s1);
            atomicAdd(&d_sumsq[o1], q1);
            atomicAdd(&d_sum[o2], s2);
            atomicAdd(&d_sumsq[o2], q2);
        }
    }
}

// ---------------------------------------------------------------------------
// K5: finalize BN statistics.
// ---------------------------------------------------------------------------
__global__ void k_stats(const float* __restrict__ gamma, const float* __restrict__ beta)
{
    int o = threadIdx.x;
    if (o < CC) {
        float mean = d_sum[o]   * (1.0f / BNT);
        float var  = d_sumsq[o] * (1.0f / BNT) - mean * mean;
        float sc   = gamma[o] * rsqrtf(var + 1e-5f);
        d_scale[o] = sc;
        d_shift[o] = beta[o] - mean * sc;
    }
}

// ---------------------------------------------------------------------------
// K6: out = scale[o]*wy + shift[o] + x
// ---------------------------------------------------------------------------
__global__ __launch_bounds__(256) void k_out(const float* __restrict__ x,
                                             float* __restrict__ out)
{
    size_t i4 = (size_t)blockIdx.x * 256 + threadIdx.x;
    int o = (int)((i4 >> 11) & 255);
    float sc = d_scale[o], sh = d_shift[o];
    float4 w  = *((const float4*)d_wy + i4);
    float4 xv = *((const float4*)x + i4);
    float4 r;
    r.x = fmaf(sc, w.x, sh) + xv.x;
    r.y = fmaf(sc, w.y, sh) + xv.y;
    r.z = fmaf(sc, w.z, sh) + xv.z;
    r.w = fmaf(sc, w.w, sh) + xv.w;
    ((float4*)out)[i4] = r;
}

// ---------------------------------------------------------------------------
extern "C" void kernel_launch(void* const* d_in, const int* in_sizes, int n_in,
                              void* d_out, int out_size)
{
    const float* x     = (const float*)d_in[0];
    const float* tw    = (const float*)d_in[1];
    const float* tb    = (const float*)d_in[2];
    const float* pw    = (const float*)d_in[3];
    const float* pb    = (const float*)d_in[4];
    const float* gw    = (const float*)d_in[5];
    const float* gb    = (const float*)d_in[6];
    const float* ww    = (const float*)d_in[7];
    const float* wb    = (const float*)d_in[8];
    const float* gamma = (const float*)d_in[9];
    const float* beta  = (const float*)d_in[10];
    float* out = (float*)d_out;

    static int smem_set = 0;
    if (!smem_set) {
        cudaFuncSetAttribute(k_conv_hmma, cudaFuncAttributeMaxDynamicSharedMemorySize, SMEM_C3);
        cudaFuncSetAttribute(k_S_hmma,    cudaFuncAttributeMaxDynamicSharedMemorySize, SMEM_S3);
        cudaFuncSetAttribute(k_M3,        cudaFuncAttributeMaxDynamicSharedMemorySize, SMEM_S3);
        cudaFuncSetAttribute(k_wy_hmma,   cudaFuncAttributeMaxDynamicSharedMemorySize, SMEM_C3);
        smem_set = 1;
    }

    k_init<<<256, 256>>>();
    k_conv_hmma<<<dim3(TT / 128, 3, BB), 256, SMEM_C3>>>(x, tw, tb, pw, pb, gw, gb);
    k_S_hmma<<<dim3(16, BB), 256, SMEM_S3>>>();
    k_M3<<<dim3(2, BB), 256, SMEM_S3>>>(ww);
    k_wy_hmma<<<dim3(TT / 128, 2, BB), 256, SMEM_C3>>>(wb);
    k_stats<<<1, 256>>>(gamma, beta);
    k_out<<<8192, 256>>>(x, out);
}

// round 11
// speedup vs baseline: 1.3321x; 1.0864x over previous
#include <cuda_runtime.h>
#include <cstdint>

#define BB 4
#define CC 256
#define CI 128
#define TT 8192
#define NN 4096
#define BNT (BB*TT)

// Scratch (device globals; no allocation allowed)
__device__ float d_theta[BB*CI*TT];   // 16 MB
__device__ float d_phi[BB*CI*NN];     // 8 MB
__device__ float d_g[BB*CI*NN];       // 8 MB
__device__ float d_S[BB*CI*CI];       // 256 KB
__device__ float d_M[BB*CC*CI];       // 512 KB
__device__ float d_wy[BB*CC*TT];      // 32 MB
__device__ float d_sum[CC];
__device__ float d_sumsq[CC];
__device__ float d_scale[CC];
__device__ float d_shift[CC];

// ---------------- tf32 mma.sync helper (raw fp32 bits; BN cancels the
// systematic truncation bias as a per-channel affine distortion) ------------
__device__ __forceinline__ void mma_tf32(float* d, const uint32_t* a, const uint32_t* b) {
    asm("mma.sync.aligned.m16n8k8.row.col.f32.tf32.tf32.f32 "
        "{%0,%1,%2,%3}, {%4,%5,%6,%7}, {%8,%9}, {%0,%1,%2,%3};"
        : "+f"(d[0]), "+f"(d[1]), "+f"(d[2]), "+f"(d[3])
        : "r"(a[0]), "r"(a[1]), "r"(a[2]), "r"(a[3]), "r"(b[0]), "r"(b[1]));
}

// ---------------- cp.async helpers ------------------------------------------
__device__ __forceinline__ uint32_t smem_u32(const void* p) {
    uint32_t a;
    asm("{ .reg .u64 t; cvta.to.shared.u64 t, %1; cvt.u32.u64 %0, t; }" : "=r"(a) : "l"(p));
    return a;
}
__device__ __forceinline__ void cp16(uint32_t dst, const void* src) {
    asm volatile("cp.async.cg.shared.global [%0], [%1], 16;" :: "r"(dst), "l"(src));
}
#define CP_COMMIT() asm volatile("cp.async.commit_group;" ::: "memory")
#define CP_WAIT1()  asm volatile("cp.async.wait_group 1;" ::: "memory")
#define CP_WAIT0()  asm volatile("cp.async.wait_group 0;" ::: "memory")

// SMEM geometry: per stage, A chunk 128 rows x 32 k (row-major, pad 4) and
// B chunk 32 k x 128 cols (pad 8). Two stages (double buffer).
//   A frag loads: bank = (4*lr + lq + 8ks) % 32  -> conflict-free
//   B frag loads: bank = (8*lq + lr) % 32        -> conflict-free
//   S's B (row-major like A): bank = (4*lr + lq) -> conflict-free
#define RPA 36
#define RPB 136
#define ASZ (128*RPA)          // 4608 u32
#define BSZ (32*RPB)           // 4352 u32
#define STG_C (ASZ + BSZ)      // 8960 u32
#define SMEM_CONV (2*STG_C*4)  // 71680 B
#define STG_S (ASZ + ASZ)      // 9216 u32
#define SMEM_S (2*STG_S*4)     // 73728 B

// Stage 128 rows x 32 floats (A-style / S's B-style), cp.async.
__device__ __forceinline__ void stage128x32(uint32_t dstb, const float* __restrict__ src,
                                            int lds, int koff, int tid) {
#pragma unroll
    for (int i = 0; i < 4; i++) {
        int fid = i * 256 + tid;        // 0..1023
        int r = fid >> 3, q = fid & 7;
        cp16(dstb + (uint32_t)(r * RPA + q * 4) * 4,
             src + (size_t)r * lds + koff + q * 4);
    }
}
// Stage 32 k-rows x 128 floats (B-style), cp.async.
__device__ __forceinline__ void stage32x128(uint32_t dstb, const float* __restrict__ src,
                                            int lds, int koff, int t0, int tid) {
#pragma unroll
    for (int i = 0; i < 4; i++) {
        int fid = i * 256 + tid;        // 0..1023
        int k = fid >> 5, t4 = (fid & 31) << 2;
        cp16(dstb + (uint32_t)(k * RPB + t4) * 4,
             src + (size_t)(koff + k) * lds + t0 + t4);
    }
}

// ---------------------------------------------------------------------------
// K0: zero accumulators (S, M, sum, sumsq).
// ---------------------------------------------------------------------------
__global__ void k_init() {
    int i = blockIdx.x * blockDim.x + threadIdx.x;   // 0..65535
    if (i < BB*CI*CI) d_S[i] = 0.0f;
    d_M[2*i]   = 0.0f;
    d_M[2*i+1] = 0.0f;
    if (i < CC) { d_sum[i] = 0.0f; d_sumsq[i] = 0.0f; }
}

// ---------------------------------------------------------------------------
// K1: fused 1x1 convs via tf32 mma.sync + cp.async double buffer.
// Block: 128 o x 128 t, K=256 in 8 chunks of 32. w = blockIdx.y + woff
// selects theta(0) / phi(1) / g(2), so the theta slice and the phi+g slice
// can be launched on different streams.
// ---------------------------------------------------------------------------
__global__ void __launch_bounds__(256, 2) k_conv_hmma(
    const float* __restrict__ x,
    const float* __restrict__ Wt, const float* __restrict__ bt,
    const float* __restrict__ Wp, const float* __restrict__ bp,
    const float* __restrict__ Wg, const float* __restrict__ bg,
    int woff)
{
    extern __shared__ uint32_t smem[];
    const uint32_t smb = smem_u32(smem);

    const int tid = threadIdx.x;
    const int warp = tid >> 5, lane = tid & 31;
    const int wo = warp >> 1, wt = warp & 1;
    const int b  = blockIdx.z;
    const int w  = blockIdx.y + woff;
    const int t0 = blockIdx.x * 128;

    const float* W    = (w == 0) ? Wt : ((w == 1) ? Wp : Wg);
    const float* bias = (w == 0) ? bt : ((w == 1) ? bp : bg);
    const float* xb   = x + (size_t)b * CC * TT;

    float acc[2][8][4];
#pragma unroll
    for (int mi = 0; mi < 2; mi++)
#pragma unroll
        for (int nt = 0; nt < 8; nt++)
#pragma unroll
            for (int j = 0; j < 4; j++) acc[mi][nt][j] = 0.0f;

    const int lq = lane & 3, lr = lane >> 2;
    const int NC = 8;

    stage128x32(smb, W, CC, 0, tid);
    stage32x128(smb + ASZ * 4, xb, TT, 0, t0, tid);
    CP_COMMIT();

    for (int kc = 0; kc < NC; kc++) {
        if (kc + 1 < NC) {
            uint32_t ab = smb + (uint32_t)(((kc + 1) & 1) * STG_C) * 4;
            stage128x32(ab, W, CC, (kc + 1) * 32, tid);
            stage32x128(ab + ASZ * 4, xb, TT, (kc + 1) * 32, t0, tid);
            CP_COMMIT();
            CP_WAIT1();
        } else {
            CP_WAIT0();
        }
        __syncthreads();
        const uint32_t* As = smem + (kc & 1) * STG_C;
        const uint32_t* Bs = As + ASZ;
#pragma unroll
        for (int ks = 0; ks < 4; ks++) {
            int k0 = ks * 8;
            uint32_t a[2][4], bf[8][2];
#pragma unroll
            for (int mi = 0; mi < 2; mi++) {
                int ro = (wo * 2 + mi) * 16;
                a[mi][0] = As[(ro + lr) * RPA + k0 + lq];
                a[mi][1] = As[(ro + lr + 8) * RPA + k0 + lq];
                a[mi][2] = As[(ro + lr) * RPA + k0 + 4 + lq];
                a[mi][3] = As[(ro + lr + 8) * RPA + k0 + 4 + lq];
            }
            int tb = wt * 64 + lr;
#pragma unroll
            for (int nt = 0; nt < 8; nt++) {
                bf[nt][0] = Bs[(k0 + lq) * RPB + tb + nt * 8];
                bf[nt][1] = Bs[(k0 + 4 + lq) * RPB + tb + nt * 8];
            }
#pragma unroll
            for (int mi = 0; mi < 2; mi++)
#pragma unroll
                for (int nt = 0; nt < 8; nt++)
                    mma_tf32(acc[mi][nt], a[mi], bf[nt]);
        }
        __syncthreads();
    }

    // Epilogue. D frag: d0=D[lr][2lq], d1=D[lr][2lq+1], d2=D[lr+8][2lq], d3=D[lr+8][2lq+1]
    if (w == 0) {
        float* dst = d_theta + (size_t)b * CI * TT;
#pragma unroll
        for (int mi = 0; mi < 2; mi++) {
            int o1 = wo * 32 + mi * 16 + lr;
            int o2 = o1 + 8;
            float bz1 = bias[o1], bz2 = bias[o2];
#pragma unroll
            for (int nt = 0; nt < 8; nt++) {
                int t = t0 + wt * 64 + nt * 8 + 2 * lq;
                *(float2*)(dst + (size_t)o1 * TT + t) =
                    make_float2(acc[mi][nt][0] + bz1, acc[mi][nt][1] + bz1);
                *(float2*)(dst + (size_t)o2 * TT + t) =
                    make_float2(acc[mi][nt][2] + bz2, acc[mi][nt][3] + bz2);
            }
        }
    } else {
        float* dst = ((w == 1) ? d_phi : d_g) + (size_t)b * CI * NN;
#pragma unroll
        for (int mi = 0; mi < 2; mi++) {
            int o1 = wo * 32 + mi * 16 + lr;
            int o2 = o1 + 8;
            float bz1 = bias[o1], bz2 = bias[o2];
#pragma unroll
            for (int nt = 0; nt < 8; nt++) {
                int n = (t0 >> 1) + wt * 32 + nt * 4 + lq;
                dst[(size_t)o1 * NN + n] = fmaxf(acc[mi][nt][0], acc[mi][nt][1]) + bz1;
                dst[(size_t)o2 * NN + n] = fmaxf(acc[mi][nt][2], acc[mi][nt][3]) + bz2;
            }
        }
    }
}

// ---------------------------------------------------------------------------
// K2: S[b,a,ci] = sum_n phi[b,a,n]*g[b,ci,n], tf32 mma + cp.async pipeline.
// Split-K: 16 slabs of 256 n (8 chunks of 32). Atomic reduce into d_S.
// ---------------------------------------------------------------------------
__global__ void __launch_bounds__(256, 2) k_S_hmma()
{
    extern __shared__ uint32_t smem[];
    const uint32_t smb = smem_u32(smem);

    const int tid = threadIdx.x;
    const int warp = tid >> 5, lane = tid & 31;
    const int wo = warp >> 1, wt = warp & 1;
    const int b  = blockIdx.y;
    const int n0 = blockIdx.x * 256;

    const float* P = d_phi + (size_t)b * CI * NN;
    const float* G = d_g   + (size_t)b * CI * NN;

    float acc[2][8][4];
#pragma unroll
    for (int mi = 0; mi < 2; mi++)
#pragma unroll
        for (int nt = 0; nt < 8; nt++)
#pragma unroll
            for (int j = 0; j < 4; j++) acc[mi][nt][j] = 0.0f;

    const int lq = lane & 3, lr = lane >> 2;
    const int NC = 8;

    stage128x32(smb, P, NN, n0, tid);
    stage128x32(smb + ASZ * 4, G, NN, n0, tid);
    CP_COMMIT();

    for (int kc = 0; kc < NC; kc++) {
        if (kc + 1 < NC) {
            uint32_t ab = smb + (uint32_t)(((kc + 1) & 1) * STG_S) * 4;
            stage128x32(ab, P, NN, n0 + (kc + 1) * 32, tid);
            stage128x32(ab + ASZ * 4, G, NN, n0 + (kc + 1) * 32, tid);
            CP_COMMIT();
            CP_WAIT1();
        } else {
            CP_WAIT0();
        }
        __syncthreads();
        const uint32_t* As  = smem + (kc & 1) * STG_S;
        const uint32_t* Bs2 = As + ASZ;
#pragma unroll
        for (int ks = 0; ks < 4; ks++) {
            int k0 = ks * 8;
            uint32_t a[2][4], bf[8][2];
#pragma unroll
            for (int mi = 0; mi < 2; mi++) {
                int ro = (wo * 2 + mi) * 16;
                a[mi][0] = As[(ro + lr) * RPA + k0 + lq];
                a[mi][1] = As[(ro + lr + 8) * RPA + k0 + lq];
                a[mi][2] = As[(ro + lr) * RPA + k0 + 4 + lq];
                a[mi][3] = As[(ro + lr + 8) * RPA + k0 + 4 + lq];
            }
#pragma unroll
            for (int nt = 0; nt < 8; nt++) {
                int n = wt * 64 + nt * 8 + lr;
                bf[nt][0] = Bs2[n * RPA + k0 + lq];
                bf[nt][1] = Bs2[n * RPA + k0 + 4 + lq];
            }
#pragma unroll
            for (int mi = 0; mi < 2; mi++)
#pragma unroll
                for (int nt = 0; nt < 8; nt++)
                    mma_tf32(acc[mi][nt], a[mi], bf[nt]);
        }
        __syncthreads();
    }

    float* Sp = d_S + (size_t)b * CI * CI;
#pragma unroll
    for (int mi = 0; mi < 2; mi++) {
        int a1 = wo * 32 + mi * 16 + lr;
        int a2 = a1 + 8;
#pragma unroll
        for (int nt = 0; nt < 8; nt++) {
            int ci = wt * 64 + nt * 8 + 2 * lq;
            atomicAdd(&Sp[(size_t)a1 * CI + ci],     acc[mi][nt][0]);
            atomicAdd(&Sp[(size_t)a1 * CI + ci + 1], acc[mi][nt][1]);
            atomicAdd(&Sp[(size_t)a2 * CI + ci],     acc[mi][nt][2]);
            atomicAdd(&Sp[(size_t)a2 * CI + ci + 1], acc[mi][nt][3]);
        }
    }
}

// ---------------------------------------------------------------------------
// K3: M[b,o,a] = (1/N) * sum_k w_w[o,k] * S[b,a,k]. Split-k SMEM GEMM (fp32).
// ---------------------------------------------------------------------------
__global__ __launch_bounds__(256) void k_M2(const float* __restrict__ ww)
{
    __shared__ float ws[32][65];
    __shared__ float ss[32][65];

    const int tid = threadIdx.x;
    const int b  = blockIdx.x >> 6;
    const int ob = (blockIdx.x >> 3) & 7;
    const int ab = (blockIdx.x >> 1) & 3;
    const int kh = (blockIdx.x & 1) * 64;

#pragma unroll
    for (int i = 0; i < 2; i++) {
        int fid = i * 256 + tid;
        int r = fid >> 4, c4 = fid & 15;
        float4 v = *(const float4*)(ww + (size_t)(ob * 32 + r) * CI + kh + 4 * c4);
        ws[r][4*c4+0] = v.x; ws[r][4*c4+1] = v.y; ws[r][4*c4+2] = v.z; ws[r][4*c4+3] = v.w;
        float4 u = *(const float4*)(d_S + (size_t)b * CI * CI + (size_t)(ab * 32 + r) * CI + kh + 4 * c4);
        ss[r][4*c4+0] = u.x; ss[r][4*c4+1] = u.y; ss[r][4*c4+2] = u.z; ss[r][4*c4+3] = u.w;
    }
    __syncthreads();

    const int ty = tid >> 3;
    const int tx = tid & 7;
    float acc[4] = {0.f, 0.f, 0.f, 0.f};
#pragma unroll
    for (int k = 0; k < 64; k++) {
        float wv = ws[ty][k];
#pragma unroll
        for (int j = 0; j < 4; j++) acc[j] = fmaf(wv, ss[4*tx+j][k], acc[j]);
    }
    const float invN = 1.0f / NN;
    float* Mp = d_M + (size_t)b * CC * CI + (size_t)(ob * 32 + ty) * CI + ab * 32 + 4 * tx;
#pragma unroll
    for (int j = 0; j < 4; j++) atomicAdd(&Mp[j], acc[j] * invN);
}

// ---------------------------------------------------------------------------
// K4: wy = M @ theta + w_b via tf32 mma + cp.async pipeline; fused BN sums.
// Block: 128 o x 128 t, K=128 in 4 chunks of 32.
// ---------------------------------------------------------------------------
__global__ void __launch_bounds__(256, 2) k_wy_hmma(const float* __restrict__ wb)
{
    extern __shared__ uint32_t smem[];
    const uint32_t smb = smem_u32(smem);

    const int tid = threadIdx.x;
    const int warp = tid >> 5, lane = tid & 31;
    const int wo = warp >> 1, wt = warp & 1;
    const int b  = blockIdx.z;
    const int o0 = blockIdx.y * 128;
    const int t0 = blockIdx.x * 128;

    const float* Mp = d_M + (size_t)b * CC * CI + (size_t)o0 * CI;
    const float* Th = d_theta + (size_t)b * CI * TT;

    float acc[2][8][4];
#pragma unroll
    for (int mi = 0; mi < 2; mi++)
#pragma unroll
        for (int nt = 0; nt < 8; nt++)
#pragma unroll
            for (int j = 0; j < 4; j++) acc[mi][nt][j] = 0.0f;

    const int lq = lane & 3, lr = lane >> 2;
    const int NC = 4;

    stage128x32(smb, Mp, CI, 0, tid);
    stage32x128(smb + ASZ * 4, Th, TT, 0, t0, tid);
    CP_COMMIT();

    for (int kc = 0; kc < NC; kc++) {
        if (kc + 1 < NC) {
            uint32_t ab = smb + (uint32_t)(((kc + 1) & 1) * STG_C) * 4;
            stage128x32(ab, Mp, CI, (kc + 1) * 32, tid);
            stage32x128(ab + ASZ * 4, Th, TT, (kc + 1) * 32, t0, tid);
            CP_COMMIT();
            CP_WAIT1();
        } else {
            CP_WAIT0();
        }
        __syncthreads();
        const uint32_t* As = smem + (kc & 1) * STG_C;
        const uint32_t* Bs = As + ASZ;
#pragma unroll
        for (int ks = 0; ks < 4; ks++) {
            int k0 = ks * 8;
            uint32_t a[2][4], bf[8][2];
#pragma unroll
            for (int mi = 0; mi < 2; mi++) {
                int ro = (wo * 2 + mi) * 16;
                a[mi][0] = As[(ro + lr) * RPA + k0 + lq];
                a[mi][1] = As[(ro + lr + 8) * RPA + k0 + lq];
                a[mi][2] = As[(ro + lr) * RPA + k0 + 4 + lq];
                a[mi][3] = As[(ro + lr + 8) * RPA + k0 + 4 + lq];
            }
            int tb = wt * 64 + lr;
#pragma unroll
            for (int nt = 0; nt < 8; nt++) {
                bf[nt][0] = Bs[(k0 + lq) * RPB + tb + nt * 8];
                bf[nt][1] = Bs[(k0 + 4 + lq) * RPB + tb + nt * 8];
            }
#pragma unroll
            for (int mi = 0; mi < 2; mi++)
#pragma unroll
                for (int nt = 0; nt < 8; nt++)
                    mma_tf32(acc[mi][nt], a[mi], bf[nt]);
        }
        __syncthreads();
    }

    float* wyp = d_wy + (size_t)b * CC * TT;
#pragma unroll
    for (int mi = 0; mi < 2; mi++) {
        int o1 = o0 + wo * 32 + mi * 16 + lr;
        int o2 = o1 + 8;
        float bz1 = wb[o1], bz2 = wb[o2];
        float s1 = 0.f, q1 = 0.f, s2 = 0.f, q2 = 0.f;
#pragma unroll
        for (int nt = 0; nt < 8; nt++) {
            int t = t0 + wt * 64 + nt * 8 + 2 * lq;
            float v0 = acc[mi][nt][0] + bz1, v1 = acc[mi][nt][1] + bz1;
            float v2 = acc[mi][nt][2] + bz2, v3 = acc[mi][nt][3] + bz2;
            s1 += v0 + v1; q1 = fmaf(v0, v0, q1); q1 = fmaf(v1, v1, q1);
            s2 += v2 + v3; q2 = fmaf(v2, v2, q2); q2 = fmaf(v3, v3, q2);
            *(float2*)(wyp + (size_t)o1 * TT + t) = make_float2(v0, v1);
            *(float2*)(wyp + (size_t)o2 * TT + t) = make_float2(v2, v3);
        }
#pragma unroll
        for (int off = 1; off < 4; off <<= 1) {
            s1 += __shfl_xor_sync(0xffffffffu, s1, off);
            q1 += __shfl_xor_sync(0xffffffffu, q1, off);
            s2 += __shfl_xor_sync(0xffffffffu, s2, off);
            q2 += __shfl_xor_sync(0xffffffffu, q2, off);
        }
        if (lq == 0) {
            atomicAdd(&d_sum[o1], s1);
            atomicAdd(&d_sumsq[o1], q1);
            atomicAdd(&d_sum[o2], s2);
            atomicAdd(&d_sumsq[o2], q2);
        }
    }
}

// ---------------------------------------------------------------------------
// K5: finalize BN statistics.
// ---------------------------------------------------------------------------
__global__ void k_stats(const float* __restrict__ gamma, const float* __restrict__ beta)
{
    int o = threadIdx.x;
    if (o < CC) {
        float mean = d_sum[o]   * (1.0f / BNT);
        float var  = d_sumsq[o] * (1.0f / BNT) - mean * mean;
        float sc   = gamma[o] * rsqrtf(var + 1e-5f);
        d_scale[o] = sc;
        d_shift[o] = beta[o] - mean * sc;
    }
}

// ---------------------------------------------------------------------------
// K6: out = scale[o]*wy + shift[o] + x
// ---------------------------------------------------------------------------
__global__ __launch_bounds__(256) void k_out(const float* __restrict__ x,
                                             float* __restrict__ out)
{
    size_t i4 = (size_t)blockIdx.x * 256 + threadIdx.x;
    int o = (int)((i4 >> 11) & 255);
    float sc = d_scale[o], sh = d_shift[o];
    float4 w  = *((const float4*)d_wy + i4);
    float4 xv = *((const float4*)x + i4);
    float4 r;
    r.x = fmaf(sc, w.x, sh) + xv.x;
    r.y = fmaf(sc, w.y, sh) + xv.y;
    r.z = fmaf(sc, w.z, sh) + xv.z;
    r.w = fmaf(sc, w.w, sh) + xv.w;
    ((float4*)out)[i4] = r;
}

// ---------------------------------------------------------------------------
// Launch: two-stream fork/join (graph-capturable).
//   s1 (high prio): init -> conv(phi,g) -> S -> M
//   s0 (default)  : conv(theta)  [backfills SMs while S/M run]
//   join          : wy -> stats -> out
// ---------------------------------------------------------------------------
extern "C" void kernel_launch(void* const* d_in, const int* in_sizes, int n_in,
                              void* d_out, int out_size)
{
    const float* x     = (const float*)d_in[0];
    const float* tw    = (const float*)d_in[1];
    const float* tb    = (const float*)d_in[2];
    const float* pw    = (const float*)d_in[3];
    const float* pb    = (const float*)d_in[4];
    const float* gw    = (const float*)d_in[5];
    const float* gb    = (const float*)d_in[6];
    const float* ww    = (const float*)d_in[7];
    const float* wb    = (const float*)d_in[8];
    const float* gamma = (const float*)d_in[9];
    const float* beta  = (const float*)d_in[10];
    float* out = (float*)d_out;

    static cudaStream_t s1 = nullptr;
    static cudaEvent_t eF = nullptr, eJ = nullptr;
    static int init_done = 0;
    if (!init_done) {
        cudaFuncSetAttribute(k_conv_hmma, cudaFuncAttributeMaxDynamicSharedMemorySize, SMEM_CONV);
        cudaFuncSetAttribute(k_S_hmma,    cudaFuncAttributeMaxDynamicSharedMemorySize, SMEM_S);
        cudaFuncSetAttribute(k_wy_hmma,   cudaFuncAttributeMaxDynamicSharedMemorySize, SMEM_CONV);
        int lo, hi;
        cudaDeviceGetStreamPriorityRange(&lo, &hi);
        cudaStreamCreateWithPriority(&s1, cudaStreamNonBlocking, hi);
        cudaEventCreateWithFlags(&eF, cudaEventDisableTiming);
        cudaEventCreateWithFlags(&eJ, cudaEventDisableTiming);
        init_done = 1;
    }

    // Fork: s1 branches off the main (captured) stream.
    cudaEventRecord(eF, 0);
    cudaStreamWaitEvent(s1, eF, 0);

    // s1 chain: init, phi+g convs, S, M.
    k_init<<<256, 256, 0, s1>>>();
    k_conv_hmma<<<dim3(TT / 128, 2, BB), 256, SMEM_CONV, s1>>>(x, tw, tb, pw, pb, gw, gb, 1);
    k_S_hmma<<<dim3(16, BB), 256, SMEM_S, s1>>>();
    k_M2<<<256, 256, 0, s1>>>(ww);
    cudaEventRecord(eJ, s1);

    // main stream: theta conv runs concurrently (backfills idle SMs during S/M).
    k_conv_hmma<<<dim3(TT / 128, 1, BB), 256, SMEM_CONV>>>(x, tw, tb, pw, pb, gw, gb, 0);

    // Join, then the dependent tail.
    cudaStreamWaitEvent(0, eJ, 0);
    k_wy_hmma<<<dim3(TT / 128, 2, BB), 256, SMEM_CONV>>>(wb);
    k_stats<<<1, 256>>>(gamma, beta);
    k_out<<<8192, 256>>>(x, out);
}